// round 2
// baseline (speedup 1.0000x reference)
#include <cuda_runtime.h>

#define N_NODES 50000
#define N_EDGES 800000
#define D 128

// Scratch: z accumulators (atomic targets) + per-node gate.
__device__ __align__(16) float g_zlp[N_NODES * D];
__device__ __align__(16) float g_zhp[N_NODES * D];
__device__ float g_alpha[N_NODES];

// ---------------------------------------------------------------------------
// Kernel 1: zero the accumulators (atomics need clean state every call).
// ---------------------------------------------------------------------------
__global__ void zero_kernel() {
    int i = blockIdx.x * blockDim.x + threadIdx.x;
    const int n4 = N_NODES * D / 4;
    float4 z = make_float4(0.f, 0.f, 0.f, 0.f);
    if (i < n4) {
        reinterpret_cast<float4*>(g_zlp)[i] = z;
        reinterpret_cast<float4*>(g_zhp)[i] = z;
    }
}

// ---------------------------------------------------------------------------
// Kernel 2: alpha_i = sigmoid(x_i . aw + ab). One warp per node.
// Writes both the scratch copy (for the GEMM) and the d_out tail.
// ---------------------------------------------------------------------------
__global__ void alpha_kernel(const float* __restrict__ x,
                             const float* __restrict__ aw,
                             const float* __restrict__ ab,
                             float* __restrict__ alpha_out) {
    int warp = (blockIdx.x * blockDim.x + threadIdx.x) >> 5;
    int lane = threadIdx.x & 31;
    if (warp >= N_NODES) return;
    float4 xv = reinterpret_cast<const float4*>(x)[warp * 32 + lane];
    float4 wv = reinterpret_cast<const float4*>(aw)[lane];
    float s = xv.x * wv.x + xv.y * wv.y + xv.z * wv.z + xv.w * wv.w;
    #pragma unroll
    for (int o = 16; o; o >>= 1) s += __shfl_xor_sync(0xFFFFFFFFu, s, o);
    if (lane == 0) {
        s += ab[0];
        float a = 1.0f / (1.0f + expf(-s));
        g_alpha[warp] = a;
        alpha_out[warp] = a;
    }
}

// ---------------------------------------------------------------------------
// Kernel 3: both SPMMs in one launch. One warp per edge.
// Each lane handles 4 contiguous channels -> gather float4, scale,
// vectorized reduction red.global.add.v4.f32 (sm_90+) into z[row].
// ---------------------------------------------------------------------------
__global__ void spmm_kernel(const int* __restrict__ lp_rows,
                            const int* __restrict__ lp_cols,
                            const float* __restrict__ lp_vals,
                            const int* __restrict__ hp_rows,
                            const int* __restrict__ hp_cols,
                            const float* __restrict__ hp_vals,
                            const float* __restrict__ x) {
    long long gwarp = (long long)(blockIdx.x) * (blockDim.x >> 5) + (threadIdx.x >> 5);
    int lane = threadIdx.x & 31;
    if (gwarp >= 2LL * N_EDGES) return;

    const int* rows;
    const int* cols;
    const float* vals;
    float* z;
    int e;
    if (gwarp < N_EDGES) {
        e = (int)gwarp;
        rows = lp_rows; cols = lp_cols; vals = lp_vals; z = g_zlp;
    } else {
        e = (int)(gwarp - N_EDGES);
        rows = hp_rows; cols = hp_cols; vals = hp_vals; z = g_zhp;
    }

    int r = __ldg(rows + e);
    int c = __ldg(cols + e);
    float v = __ldg(vals + e);

    float4 xv = __ldg(reinterpret_cast<const float4*>(x) + (long long)c * 32 + lane);
    float4 p = make_float4(xv.x * v, xv.y * v, xv.z * v, xv.w * v);

    float* dst = z + (long long)r * D + lane * 4;
    asm volatile("red.global.add.v4.f32 [%0], {%1, %2, %3, %4};"
                 :: "l"(dst), "f"(p.x), "f"(p.y), "f"(p.z), "f"(p.w)
                 : "memory");
}

// ---------------------------------------------------------------------------
// Kernel 4: z_mix = a*z_lp + (1-a)*z_hp ; out = relu(z_mix @ W^T + b).
// Block = 256 threads (8 warps), 32 rows per block, 4 rows per warp.
// W transposed into smem with stride 132 (pad 4) -> conflict-free float4
// loads AND float4-aligned rows. Each lane owns 4 output cols.
// ---------------------------------------------------------------------------
__global__ void __launch_bounds__(256)
mix_gemm_kernel(const float* __restrict__ W,
                const float* __restrict__ b,
                float* __restrict__ out) {
    extern __shared__ float sm[];
    float* Wt = sm;               // [128][132]
    float* zs = sm + 128 * 132;   // [32][128]

    int tid = threadIdx.x;

    // Load + transpose W: Wt[k][c] = W[c*128 + k]
    for (int idx = tid; idx < D * D; idx += 256) {
        int c = idx >> 7;
        int k = idx & 127;
        Wt[k * 132 + c] = W[idx];
    }
    __syncthreads();

    int warp = tid >> 5;
    int lane = tid & 31;
    int rowbase = blockIdx.x * 32 + warp * 4;

    // Build z_mix rows in smem
    #pragma unroll
    for (int rr = 0; rr < 4; rr++) {
        int row = rowbase + rr;
        float4 zm = make_float4(0.f, 0.f, 0.f, 0.f);
        if (row < N_NODES) {
            float a  = g_alpha[row];
            float na = 1.0f - a;
            float4 lp = reinterpret_cast<const float4*>(g_zlp)[row * 32 + lane];
            float4 hp = reinterpret_cast<const float4*>(g_zhp)[row * 32 + lane];
            zm.x = a * lp.x + na * hp.x;
            zm.y = a * lp.y + na * hp.y;
            zm.z = a * lp.z + na * hp.z;
            zm.w = a * lp.w + na * hp.w;
        }
        reinterpret_cast<float4*>(zs + (warp * 4 + rr) * D)[lane] = zm;
    }
    __syncwarp();

    float acc[4][4];
    #pragma unroll
    for (int i = 0; i < 4; i++)
        #pragma unroll
        for (int j = 0; j < 4; j++) acc[i][j] = 0.f;

    #pragma unroll 4
    for (int k0 = 0; k0 < D; k0 += 4) {
        float4 w4[4];
        #pragma unroll
        for (int j = 0; j < 4; j++)
            w4[j] = reinterpret_cast<const float4*>(Wt + (k0 + j) * 132)[lane];

        #pragma unroll
        for (int rr = 0; rr < 4; rr++) {
            float4 z4 = *reinterpret_cast<const float4*>(zs + (warp * 4 + rr) * D + k0);
            float zc0 = z4.x, zc1 = z4.y, zc2 = z4.z, zc3 = z4.w;
            acc[rr][0] += zc0 * w4[0].x + zc1 * w4[1].x + zc2 * w4[2].x + zc3 * w4[3].x;
            acc[rr][1] += zc0 * w4[0].y + zc1 * w4[1].y + zc2 * w4[2].y + zc3 * w4[3].y;
            acc[rr][2] += zc0 * w4[0].z + zc1 * w4[1].z + zc2 * w4[2].z + zc3 * w4[3].z;
            acc[rr][3] += zc0 * w4[0].w + zc1 * w4[1].w + zc2 * w4[2].w + zc3 * w4[3].w;
        }
    }

    float4 bv = reinterpret_cast<const float4*>(b)[lane];
    #pragma unroll
    for (int rr = 0; rr < 4; rr++) {
        int row = rowbase + rr;
        if (row < N_NODES) {
            float4 o;
            o.x = fmaxf(acc[rr][0] + bv.x, 0.f);
            o.y = fmaxf(acc[rr][1] + bv.y, 0.f);
            o.z = fmaxf(acc[rr][2] + bv.z, 0.f);
            o.w = fmaxf(acc[rr][3] + bv.w, 0.f);
            reinterpret_cast<float4*>(out + (long long)row * D)[lane] = o;
        }
    }
}

// ---------------------------------------------------------------------------
extern "C" void kernel_launch(void* const* d_in, const int* in_sizes, int n_in,
                              void* d_out, int out_size) {
    const float* x   = (const float*)d_in[0];
    const int*   lpr = (const int*)  d_in[1];
    const int*   lpc = (const int*)  d_in[2];
    const float* lpv = (const float*)d_in[3];
    const int*   hpr = (const int*)  d_in[4];
    const int*   hpc = (const int*)  d_in[5];
    const float* hpv = (const float*)d_in[6];
    const float* aw  = (const float*)d_in[7];
    const float* ab  = (const float*)d_in[8];
    const float* W   = (const float*)d_in[9];
    const float* b   = (const float*)d_in[10];

    float* out       = (float*)d_out;
    float* alpha_out = out + (long long)N_NODES * D;

    const int smem_bytes = (128 * 132 + 32 * 128) * sizeof(float);  // 83968
    cudaFuncSetAttribute(mix_gemm_kernel,
                         cudaFuncAttributeMaxDynamicSharedMemorySize, smem_bytes);

    // zero accumulators
    zero_kernel<<<(N_NODES * D / 4 + 255) / 256, 256>>>();
    // per-node gate (writes d_out tail too)
    alpha_kernel<<<(N_NODES * 32 + 255) / 256, 256>>>(x, aw, ab, alpha_out);
    // both SPMMs: one warp per edge, 2*N_EDGES warps, 8 warps per block
    spmm_kernel<<<(2 * N_EDGES) / 8, 256>>>(lpr, lpc, lpv, hpr, hpc, hpv, x);
    // mix + dense GEMM + relu
    mix_gemm_kernel<<<(N_NODES + 31) / 32, 256, smem_bytes>>>(W, b, out);
}

// round 3
// speedup vs baseline: 1.6199x; 1.6199x over previous
#include <cuda_runtime.h>

#define N_NODES 50000
#define N_EDGES 800000
#define D 128
#define TOT_EDGES (2 * N_EDGES)

// ---------------------------------------------------------------------------
// Static scratch (no allocations allowed).
// ---------------------------------------------------------------------------
__device__ float g_alpha[N_NODES];
__device__ int   g_count[N_NODES];
__device__ int   g_start[N_NODES + 1];
__device__ int   g_cursor[N_NODES];
__device__ __align__(16) int2  g_edges[TOT_EDGES + 64];   // (col, scaled_val)
__device__ __align__(16) float g_zmix[N_NODES * D];

// ---------------------------------------------------------------------------
// K0: zero the row counters.
// ---------------------------------------------------------------------------
__global__ void zero_counts_kernel() {
    int i = blockIdx.x * blockDim.x + threadIdx.x;
    if (i < N_NODES) g_count[i] = 0;
}

// ---------------------------------------------------------------------------
// K1: alpha_i = sigmoid(x_i . aw + ab). One warp per node.
// ---------------------------------------------------------------------------
__global__ void alpha_kernel(const float* __restrict__ x,
                             const float* __restrict__ aw,
                             const float* __restrict__ ab,
                             float* __restrict__ alpha_out) {
    int warp = (blockIdx.x * blockDim.x + threadIdx.x) >> 5;
    int lane = threadIdx.x & 31;
    if (warp >= N_NODES) return;
    float4 xv = reinterpret_cast<const float4*>(x)[warp * 32 + lane];
    float4 wv = reinterpret_cast<const float4*>(aw)[lane];
    float s = xv.x * wv.x + xv.y * wv.y + xv.z * wv.z + xv.w * wv.w;
    #pragma unroll
    for (int o = 16; o; o >>= 1) s += __shfl_xor_sync(0xFFFFFFFFu, s, o);
    if (lane == 0) {
        s += ab[0];
        float a = 1.0f / (1.0f + expf(-s));
        g_alpha[warp] = a;
        alpha_out[warp] = a;
    }
}

// ---------------------------------------------------------------------------
// K2: histogram of destination rows over both edge streams.
// ---------------------------------------------------------------------------
__global__ void hist_kernel(const int* __restrict__ lp_rows,
                            const int* __restrict__ hp_rows) {
    int i = blockIdx.x * blockDim.x + threadIdx.x;
    if (i >= TOT_EDGES) return;
    int r = (i < N_EDGES) ? __ldg(lp_rows + i) : __ldg(hp_rows + (i - N_EDGES));
    atomicAdd(&g_count[r], 1);   // no return use -> REDG
}

// ---------------------------------------------------------------------------
// K3: exclusive prefix sum of g_count -> g_start, g_cursor. Single block.
// ---------------------------------------------------------------------------
#define SCAN_T 1024
#define SCAN_CH 49   // 1024*49 = 50176 >= 50000
__global__ void __launch_bounds__(SCAN_T)
scan_kernel() {
    __shared__ int partial[SCAN_T];
    int t = threadIdx.x;
    int base = t * SCAN_CH;

    int sum = 0;
    #pragma unroll
    for (int i = 0; i < SCAN_CH; i++) {
        int idx = base + i;
        if (idx < N_NODES) sum += g_count[idx];
    }
    partial[t] = sum;
    __syncthreads();

    // Hillis-Steele inclusive scan over 1024 partials
    #pragma unroll
    for (int off = 1; off < SCAN_T; off <<= 1) {
        int v = (t >= off) ? partial[t - off] : 0;
        __syncthreads();
        partial[t] += v;
        __syncthreads();
    }

    int run = (t > 0) ? partial[t - 1] : 0;  // exclusive offset for this chunk
    #pragma unroll
    for (int i = 0; i < SCAN_CH; i++) {
        int idx = base + i;
        if (idx < N_NODES) {
            g_start[idx]  = run;
            g_cursor[idx] = run;
            run += g_count[idx];
        }
    }
    if (t == SCAN_T - 1) g_start[N_NODES] = partial[SCAN_T - 1];
}

// ---------------------------------------------------------------------------
// K4: scatter edges into row-bucketed list, pre-scaled by the gate.
//     lp edge (r,c,v) -> val = alpha[r]*v ; hp edge -> val = (1-alpha[r])*v
// ---------------------------------------------------------------------------
__global__ void scatter_kernel(const int* __restrict__ lp_rows,
                               const int* __restrict__ lp_cols,
                               const float* __restrict__ lp_vals,
                               const int* __restrict__ hp_rows,
                               const int* __restrict__ hp_cols,
                               const float* __restrict__ hp_vals) {
    int i = blockIdx.x * blockDim.x + threadIdx.x;
    if (i >= TOT_EDGES) return;
    int r, c; float v;
    if (i < N_EDGES) {
        r = __ldg(lp_rows + i);
        c = __ldg(lp_cols + i);
        v = __ldg(lp_vals + i) * g_alpha[r];
    } else {
        int e = i - N_EDGES;
        r = __ldg(hp_rows + e);
        c = __ldg(hp_cols + e);
        v = __ldg(hp_vals + e) * (1.0f - g_alpha[r]);
    }
    int pos = atomicAdd(&g_cursor[r], 1);
    g_edges[pos] = make_int2(c, __float_as_int(v));
}

// ---------------------------------------------------------------------------
// K5: per-row gather-accumulate: z_mix[r] = sum_e val_e * x[col_e].
//     One warp per row; each lane owns 4 channels; registers accumulate,
//     single float4 store. Padding lanes use col=0, val=0 (row 0 stays hot
//     in L1, contribution is zero).
// ---------------------------------------------------------------------------
__global__ void __launch_bounds__(256)
gather_kernel(const float* __restrict__ x) {
    int warp = (blockIdx.x * blockDim.x + threadIdx.x) >> 5;
    int lane = threadIdx.x & 31;
    if (warp >= N_NODES) return;

    int s = g_start[warp];
    int e = g_start[warp + 1];

    const float4* x4 = reinterpret_cast<const float4*>(x);
    float4 acc0 = make_float4(0.f, 0.f, 0.f, 0.f);
    float4 acc1 = make_float4(0.f, 0.f, 0.f, 0.f);

    for (int base = s; base < e; base += 32) {
        int2 ed = make_int2(0, 0);
        if (base + lane < e) ed = __ldg(&g_edges[base + lane]);
        float myv = __int_as_float(ed.y);

        #pragma unroll
        for (int j = 0; j < 32; j += 2) {
            int   c0 = __shfl_sync(0xFFFFFFFFu, ed.x, j);
            float v0 = __shfl_sync(0xFFFFFFFFu, myv,  j);
            int   c1 = __shfl_sync(0xFFFFFFFFu, ed.x, j + 1);
            float v1 = __shfl_sync(0xFFFFFFFFu, myv,  j + 1);
            float4 xv0 = __ldg(x4 + (long long)c0 * 32 + lane);
            float4 xv1 = __ldg(x4 + (long long)c1 * 32 + lane);
            acc0.x += v0 * xv0.x; acc0.y += v0 * xv0.y;
            acc0.z += v0 * xv0.z; acc0.w += v0 * xv0.w;
            acc1.x += v1 * xv1.x; acc1.y += v1 * xv1.y;
            acc1.z += v1 * xv1.z; acc1.w += v1 * xv1.w;
        }
    }

    float4 acc;
    acc.x = acc0.x + acc1.x; acc.y = acc0.y + acc1.y;
    acc.z = acc0.z + acc1.z; acc.w = acc0.w + acc1.w;
    reinterpret_cast<float4*>(g_zmix)[(long long)warp * 32 + lane] = acc;
}

// ---------------------------------------------------------------------------
// K6: out = relu(z_mix @ W^T + b).
// 512 threads (16 warps), 64 rows/block, 4 rows/warp, each lane owns 4 cols.
// Wt in smem stride 132 (conflict-free float4), z rows staged in smem and
// read as warp-broadcast loads (N=1).
// ---------------------------------------------------------------------------
__global__ void __launch_bounds__(512, 2)
gemm_kernel(const float* __restrict__ W,
            const float* __restrict__ b,
            float* __restrict__ out) {
    extern __shared__ float sm[];
    float* Wt = sm;               // [128][132]
    float* zs = sm + 128 * 132;   // [64][128]

    int tid  = threadIdx.x;
    int warp = tid >> 5;
    int lane = tid & 31;

    // Load + transpose W: Wt[k][c] = W[c*128 + k]
    for (int idx = tid; idx < D * D; idx += 512) {
        int c = idx >> 7;
        int k = idx & 127;
        Wt[k * 132 + c] = W[idx];
    }

    int rowbase = blockIdx.x * 64 + warp * 4;

    // Stage this warp's 4 z rows
    #pragma unroll
    for (int rr = 0; rr < 4; rr++) {
        int row = rowbase + rr;
        float4 zm = make_float4(0.f, 0.f, 0.f, 0.f);
        if (row < N_NODES)
            zm = reinterpret_cast<const float4*>(g_zmix)[(long long)row * 32 + lane];
        reinterpret_cast<float4*>(zs + (warp * 4 + rr) * D)[lane] = zm;
    }
    __syncthreads();

    float acc[4][4];
    #pragma unroll
    for (int i = 0; i < 4; i++)
        #pragma unroll
        for (int j = 0; j < 4; j++) acc[i][j] = 0.f;

    #pragma unroll 4
    for (int k0 = 0; k0 < D; k0 += 4) {
        float4 w4[4];
        #pragma unroll
        for (int j = 0; j < 4; j++)
            w4[j] = reinterpret_cast<const float4*>(Wt + (k0 + j) * 132)[lane];

        #pragma unroll
        for (int rr = 0; rr < 4; rr++) {
            float4 z4 = *reinterpret_cast<const float4*>(zs + (warp * 4 + rr) * D + k0);
            acc[rr][0] += z4.x * w4[0].x + z4.y * w4[1].x + z4.z * w4[2].x + z4.w * w4[3].x;
            acc[rr][1] += z4.x * w4[0].y + z4.y * w4[1].y + z4.z * w4[2].y + z4.w * w4[3].y;
            acc[rr][2] += z4.x * w4[0].z + z4.y * w4[1].z + z4.z * w4[2].z + z4.w * w4[3].z;
            acc[rr][3] += z4.x * w4[0].w + z4.y * w4[1].w + z4.z * w4[2].w + z4.w * w4[3].w;
        }
    }

    float4 bv = reinterpret_cast<const float4*>(b)[lane];
    #pragma unroll
    for (int rr = 0; rr < 4; rr++) {
        int row = rowbase + rr;
        if (row < N_NODES) {
            float4 o;
            o.x = fmaxf(acc[rr][0] + bv.x, 0.f);
            o.y = fmaxf(acc[rr][1] + bv.y, 0.f);
            o.z = fmaxf(acc[rr][2] + bv.z, 0.f);
            o.w = fmaxf(acc[rr][3] + bv.w, 0.f);
            reinterpret_cast<float4*>(out + (long long)row * D)[lane] = o;
        }
    }
}

// ---------------------------------------------------------------------------
extern "C" void kernel_launch(void* const* d_in, const int* in_sizes, int n_in,
                              void* d_out, int out_size) {
    const float* x   = (const float*)d_in[0];
    const int*   lpr = (const int*)  d_in[1];
    const int*   lpc = (const int*)  d_in[2];
    const float* lpv = (const float*)d_in[3];
    const int*   hpr = (const int*)  d_in[4];
    const int*   hpc = (const int*)  d_in[5];
    const float* hpv = (const float*)d_in[6];
    const float* aw  = (const float*)d_in[7];
    const float* ab  = (const float*)d_in[8];
    const float* W   = (const float*)d_in[9];
    const float* b   = (const float*)d_in[10];

    float* out       = (float*)d_out;
    float* alpha_out = out + (long long)N_NODES * D;

    const int gemm_smem = (128 * 132 + 64 * 128) * sizeof(float);  // 100352
    cudaFuncSetAttribute(gemm_kernel,
                         cudaFuncAttributeMaxDynamicSharedMemorySize, gemm_smem);

    zero_counts_kernel<<<(N_NODES + 255) / 256, 256>>>();
    alpha_kernel<<<(N_NODES * 32 + 255) / 256, 256>>>(x, aw, ab, alpha_out);
    hist_kernel<<<(TOT_EDGES + 255) / 256, 256>>>(lpr, hpr);
    scan_kernel<<<1, SCAN_T>>>();
    scatter_kernel<<<(TOT_EDGES + 255) / 256, 256>>>(lpr, lpc, lpv, hpr, hpc, hpv);
    gather_kernel<<<(N_NODES + 7) / 8, 256>>>(x);
    gemm_kernel<<<(N_NODES + 63) / 64, 512, gemm_smem>>>(W, b, out);
}

// round 4
// speedup vs baseline: 2.2705x; 1.4016x over previous
#include <cuda_runtime.h>

#define N_NODES 50000
#define N_EDGES 800000
#define D 128
#define TOT_EDGES (2 * N_EDGES)

#define SCAN_BLK 512
#define SCAN_NBLK ((N_NODES + SCAN_BLK - 1) / SCAN_BLK)   // 98

// ---------------------------------------------------------------------------
// Static scratch (no allocations allowed).
// ---------------------------------------------------------------------------
__device__ float g_alpha[N_NODES];
__device__ int   g_count[N_NODES];
__device__ int   g_start[N_NODES + 1];
__device__ int   g_cursor[N_NODES];
__device__ int   g_bsum[SCAN_NBLK];
__device__ int   g_boff[SCAN_NBLK];
__device__ __align__(16) int2  g_edges[TOT_EDGES + 64];   // (col, scaled_val)
__device__ __align__(16) float g_zmix[N_NODES * D];

// ---------------------------------------------------------------------------
// K0: zero the row counters.
// ---------------------------------------------------------------------------
__global__ void zero_counts_kernel() {
    int i = blockIdx.x * blockDim.x + threadIdx.x;
    if (i < N_NODES) g_count[i] = 0;
}

// ---------------------------------------------------------------------------
// K1: alpha_i = sigmoid(x_i . aw + ab). One warp per node.
// ---------------------------------------------------------------------------
__global__ void alpha_kernel(const float* __restrict__ x,
                             const float* __restrict__ aw,
                             const float* __restrict__ ab,
                             float* __restrict__ alpha_out) {
    int warp = (blockIdx.x * blockDim.x + threadIdx.x) >> 5;
    int lane = threadIdx.x & 31;
    if (warp >= N_NODES) return;
    float4 xv = reinterpret_cast<const float4*>(x)[warp * 32 + lane];
    float4 wv = reinterpret_cast<const float4*>(aw)[lane];
    float s = xv.x * wv.x + xv.y * wv.y + xv.z * wv.z + xv.w * wv.w;
    #pragma unroll
    for (int o = 16; o; o >>= 1) s += __shfl_xor_sync(0xFFFFFFFFu, s, o);
    if (lane == 0) {
        s += ab[0];
        float a = 1.0f / (1.0f + expf(-s));
        g_alpha[warp] = a;
        alpha_out[warp] = a;
    }
}

// ---------------------------------------------------------------------------
// K2: histogram of destination rows over both edge streams.
// ---------------------------------------------------------------------------
__global__ void hist_kernel(const int* __restrict__ lp_rows,
                            const int* __restrict__ hp_rows) {
    int i = blockIdx.x * blockDim.x + threadIdx.x;
    if (i >= TOT_EDGES) return;
    int r = (i < N_EDGES) ? __ldg(lp_rows + i) : __ldg(hp_rows + (i - N_EDGES));
    atomicAdd(&g_count[r], 1);   // no return use -> REDG
}

// ---------------------------------------------------------------------------
// K3a: per-block exclusive scan of g_count -> local prefix in g_start,
//      block total in g_bsum. Warp-shuffle scan + smem warp totals.
// ---------------------------------------------------------------------------
__global__ void __launch_bounds__(SCAN_BLK)
scan1_kernel() {
    __shared__ int wsum[SCAN_BLK / 32];
    int t = threadIdx.x;
    int i = blockIdx.x * SCAN_BLK + t;
    int lane = t & 31;
    int wid = t >> 5;

    int v = (i < N_NODES) ? g_count[i] : 0;

    // inclusive warp scan
    int inc = v;
    #pragma unroll
    for (int o = 1; o < 32; o <<= 1) {
        int n = __shfl_up_sync(0xFFFFFFFFu, inc, o);
        if (lane >= o) inc += n;
    }
    if (lane == 31) wsum[wid] = inc;
    __syncthreads();

    if (wid == 0) {
        int ws = (lane < SCAN_BLK / 32) ? wsum[lane] : 0;
        int wi = ws;
        #pragma unroll
        for (int o = 1; o < SCAN_BLK / 32; o <<= 1) {
            int n = __shfl_up_sync(0xFFFFFFFFu, wi, o);
            if (lane >= o) wi += n;
        }
        if (lane < SCAN_BLK / 32) wsum[lane] = wi - ws;  // exclusive warp offsets
        if (lane == SCAN_BLK / 32 - 1) g_bsum[blockIdx.x] = wi;  // block total
    }
    __syncthreads();

    int excl = inc - v + wsum[wid];
    if (i < N_NODES) g_start[i] = excl;
}

// ---------------------------------------------------------------------------
// K3b: exclusive scan of the 98 block sums (single warp does it).
// ---------------------------------------------------------------------------
__global__ void scan2_kernel() {
    int lane = threadIdx.x;   // 128 threads, 4 warps; warp 0 works
    if (lane >= 128) return;
    // serial-free: do it with one warp over ceil(98/32)=4 chunks
    if ((lane >> 5) == 0) {
        int run = 0;
        for (int base = 0; base < SCAN_NBLK; base += 32) {
            int idx = base + lane;
            int v = (idx < SCAN_NBLK) ? g_bsum[idx] : 0;
            int inc = v;
            #pragma unroll
            for (int o = 1; o < 32; o <<= 1) {
                int n = __shfl_up_sync(0xFFFFFFFFu, inc, o);
                if (lane >= o) inc += n;
            }
            if (idx < SCAN_NBLK) g_boff[idx] = run + inc - v;
            run += __shfl_sync(0xFFFFFFFFu, inc, 31);
        }
        if (lane == 0) g_start[N_NODES] = run;   // total edges
    }
}

// ---------------------------------------------------------------------------
// K3c: add block offsets, materialize cursors.
// ---------------------------------------------------------------------------
__global__ void __launch_bounds__(SCAN_BLK)
scan3_kernel() {
    int i = blockIdx.x * SCAN_BLK + threadIdx.x;
    if (i >= N_NODES) return;
    int s = g_start[i] + g_boff[blockIdx.x];
    g_start[i]  = s;
    g_cursor[i] = s;
}

// ---------------------------------------------------------------------------
// K4: scatter edges into row-bucketed list, pre-scaled by the gate.
// ---------------------------------------------------------------------------
__global__ void scatter_kernel(const int* __restrict__ lp_rows,
                               const int* __restrict__ lp_cols,
                               const float* __restrict__ lp_vals,
                               const int* __restrict__ hp_rows,
                               const int* __restrict__ hp_cols,
                               const float* __restrict__ hp_vals) {
    int i = blockIdx.x * blockDim.x + threadIdx.x;
    if (i >= TOT_EDGES) return;
    int r, c; float v;
    if (i < N_EDGES) {
        r = __ldg(lp_rows + i);
        c = __ldg(lp_cols + i);
        v = __ldg(lp_vals + i) * g_alpha[r];
    } else {
        int e = i - N_EDGES;
        r = __ldg(hp_rows + e);
        c = __ldg(hp_cols + e);
        v = __ldg(hp_vals + e) * (1.0f - g_alpha[r]);
    }
    int pos = atomicAdd(&g_cursor[r], 1);
    g_edges[pos] = make_int2(c, __float_as_int(v));
}

// ---------------------------------------------------------------------------
// K5: per-row gather-accumulate: z_mix[r] = sum_e val_e * x[col_e].
// ---------------------------------------------------------------------------
__global__ void __launch_bounds__(256)
gather_kernel(const float* __restrict__ x) {
    int warp = (blockIdx.x * blockDim.x + threadIdx.x) >> 5;
    int lane = threadIdx.x & 31;
    if (warp >= N_NODES) return;

    int s = g_start[warp];
    int e = g_start[warp + 1];

    const float4* x4 = reinterpret_cast<const float4*>(x);
    float4 acc0 = make_float4(0.f, 0.f, 0.f, 0.f);
    float4 acc1 = make_float4(0.f, 0.f, 0.f, 0.f);

    for (int base = s; base < e; base += 32) {
        int2 ed = make_int2(0, 0);
        if (base + lane < e) ed = __ldg(&g_edges[base + lane]);
        float myv = __int_as_float(ed.y);

        #pragma unroll
        for (int j = 0; j < 32; j += 2) {
            int   c0 = __shfl_sync(0xFFFFFFFFu, ed.x, j);
            float v0 = __shfl_sync(0xFFFFFFFFu, myv,  j);
            int   c1 = __shfl_sync(0xFFFFFFFFu, ed.x, j + 1);
            float v1 = __shfl_sync(0xFFFFFFFFu, myv,  j + 1);
            float4 xv0 = __ldg(x4 + (long long)c0 * 32 + lane);
            float4 xv1 = __ldg(x4 + (long long)c1 * 32 + lane);
            acc0.x += v0 * xv0.x; acc0.y += v0 * xv0.y;
            acc0.z += v0 * xv0.z; acc0.w += v0 * xv0.w;
            acc1.x += v1 * xv1.x; acc1.y += v1 * xv1.y;
            acc1.z += v1 * xv1.z; acc1.w += v1 * xv1.w;
        }
    }

    float4 acc;
    acc.x = acc0.x + acc1.x; acc.y = acc0.y + acc1.y;
    acc.z = acc0.z + acc1.z; acc.w = acc0.w + acc1.w;
    reinterpret_cast<float4*>(g_zmix)[(long long)warp * 32 + lane] = acc;
}

// ---------------------------------------------------------------------------
// K6: out = relu(z_mix @ W^T + b).
// ---------------------------------------------------------------------------
__global__ void __launch_bounds__(512, 2)
gemm_kernel(const float* __restrict__ W,
            const float* __restrict__ b,
            float* __restrict__ out) {
    extern __shared__ float sm[];
    float* Wt = sm;               // [128][132]
    float* zs = sm + 128 * 132;   // [64][128]

    int tid  = threadIdx.x;
    int warp = tid >> 5;
    int lane = tid & 31;

    for (int idx = tid; idx < D * D; idx += 512) {
        int c = idx >> 7;
        int k = idx & 127;
        Wt[k * 132 + c] = W[idx];
    }

    int rowbase = blockIdx.x * 64 + warp * 4;

    #pragma unroll
    for (int rr = 0; rr < 4; rr++) {
        int row = rowbase + rr;
        float4 zm = make_float4(0.f, 0.f, 0.f, 0.f);
        if (row < N_NODES)
            zm = reinterpret_cast<const float4*>(g_zmix)[(long long)row * 32 + lane];
        reinterpret_cast<float4*>(zs + (warp * 4 + rr) * D)[lane] = zm;
    }
    __syncthreads();

    float acc[4][4];
    #pragma unroll
    for (int i = 0; i < 4; i++)
        #pragma unroll
        for (int j = 0; j < 4; j++) acc[i][j] = 0.f;

    #pragma unroll 4
    for (int k0 = 0; k0 < D; k0 += 4) {
        float4 w4[4];
        #pragma unroll
        for (int j = 0; j < 4; j++)
            w4[j] = reinterpret_cast<const float4*>(Wt + (k0 + j) * 132)[lane];

        #pragma unroll
        for (int rr = 0; rr < 4; rr++) {
            float4 z4 = *reinterpret_cast<const float4*>(zs + (warp * 4 + rr) * D + k0);
            acc[rr][0] += z4.x * w4[0].x + z4.y * w4[1].x + z4.z * w4[2].x + z4.w * w4[3].x;
            acc[rr][1] += z4.x * w4[0].y + z4.y * w4[1].y + z4.z * w4[2].y + z4.w * w4[3].y;
            acc[rr][2] += z4.x * w4[0].z + z4.y * w4[1].z + z4.z * w4[2].z + z4.w * w4[3].z;
            acc[rr][3] += z4.x * w4[0].w + z4.y * w4[1].w + z4.z * w4[2].w + z4.w * w4[3].w;
        }
    }

    float4 bv = reinterpret_cast<const float4*>(b)[lane];
    #pragma unroll
    for (int rr = 0; rr < 4; rr++) {
        int row = rowbase + rr;
        if (row < N_NODES) {
            float4 o;
            o.x = fmaxf(acc[rr][0] + bv.x, 0.f);
            o.y = fmaxf(acc[rr][1] + bv.y, 0.f);
            o.z = fmaxf(acc[rr][2] + bv.z, 0.f);
            o.w = fmaxf(acc[rr][3] + bv.w, 0.f);
            reinterpret_cast<float4*>(out + (long long)row * D)[lane] = o;
        }
    }
}

// ---------------------------------------------------------------------------
extern "C" void kernel_launch(void* const* d_in, const int* in_sizes, int n_in,
                              void* d_out, int out_size) {
    const float* x   = (const float*)d_in[0];
    const int*   lpr = (const int*)  d_in[1];
    const int*   lpc = (const int*)  d_in[2];
    const float* lpv = (const float*)d_in[3];
    const int*   hpr = (const int*)  d_in[4];
    const int*   hpc = (const int*)  d_in[5];
    const float* hpv = (const float*)d_in[6];
    const float* aw  = (const float*)d_in[7];
    const float* ab  = (const float*)d_in[8];
    const float* W   = (const float*)d_in[9];
    const float* b   = (const float*)d_in[10];

    float* out       = (float*)d_out;
    float* alpha_out = out + (long long)N_NODES * D;

    const int gemm_smem = (128 * 132 + 64 * 128) * sizeof(float);  // 100352
    cudaFuncSetAttribute(gemm_kernel,
                         cudaFuncAttributeMaxDynamicSharedMemorySize, gemm_smem);

    zero_counts_kernel<<<(N_NODES + 255) / 256, 256>>>();
    alpha_kernel<<<(N_NODES * 32 + 255) / 256, 256>>>(x, aw, ab, alpha_out);
    hist_kernel<<<(TOT_EDGES + 255) / 256, 256>>>(lpr, hpr);
    scan1_kernel<<<SCAN_NBLK, SCAN_BLK>>>();
    scan2_kernel<<<1, 128>>>();
    scan3_kernel<<<SCAN_NBLK, SCAN_BLK>>>();
    scatter_kernel<<<(TOT_EDGES + 255) / 256, 256>>>(lpr, lpc, lpv, hpr, hpc, hpv);
    gather_kernel<<<(N_NODES + 7) / 8, 256>>>(x);
    gemm_kernel<<<(N_NODES + 63) / 64, 512, gemm_smem>>>(W, b, out);
}